// round 1
// baseline (speedup 1.0000x reference)
#include <cuda_runtime.h>
#include <cuda_bf16.h>

// Problem constants: x[32,64,128,128] f32; w1[16,64,3,3]; w2[1,16,3,3]; out[32,64,128,128] f32
#define NB   32
#define NC   64
#define NH   128
#define NW   128
#define OC1  16

// Scratch (allocation-free rule: __device__ globals)
__device__ float g_h[NB * OC1 * NH * NW];    // conv1+relu output, 33.5 MB
__device__ float g_A[NB * NH * NW];          // sigmoid attention map, 2 MB
__device__ float g_w1r[NC * 9 * OC1];        // w1 transposed to [ic][tap][oc]

// ---------------------------------------------------------------------------
// Prep: w1 [oc][ic][ky][kx] -> g_w1r [ic][tap][oc]  (oc contiguous -> LDS.128)
// ---------------------------------------------------------------------------
__global__ void prep_w1_kernel(const float* __restrict__ w1) {
    int i = blockIdx.x * 256 + threadIdx.x;
    if (i < OC1 * NC * 9) {
        int t  = i % 9;
        int ic = (i / 9) % NC;
        int oc = i / (9 * NC);
        g_w1r[(ic * 9 + t) * OC1 + oc] = w1[i];
    }
}

// ---------------------------------------------------------------------------
// conv1 + relu: x[b,64,H,W] -> g_h[b,16,H,W]
// Block: (b, 4-row tile). 256 threads: octet(16) x ocg(4) x row(4).
// Thread computes 4 out-channels x 8 consecutive pixels.
// Smem x tile skewed (+2 floats per 32) so the 8-strided window reads are
// bank-conflict-free.
// ---------------------------------------------------------------------------
#define ICC   8      // input-channel chunk
#define RPAD  134    // 128 + skew headroom (max phys index 127+2*3=133)

__global__ __launch_bounds__(256) void conv1_kernel(const float* __restrict__ x) {
    __shared__ float sx[ICC][6][RPAD];     // 25.7 KB
    __shared__ float sw[ICC][9][OC1];      //  4.5 KB

    const int b     = blockIdx.y;
    const int y0    = blockIdx.x * 4;
    const int t     = threadIdx.x;
    const int octet = t & 15;
    const int ocg   = (t >> 4) & 3;
    const int r     = t >> 6;
    const int p0    = octet * 8;

    float acc[4][8];
#pragma unroll
    for (int j = 0; j < 4; j++)
#pragma unroll
        for (int p = 0; p < 8; p++) acc[j][p] = 0.f;

    for (int ic0 = 0; ic0 < NC; ic0 += ICC) {
        // weights chunk (layout already matches [ic][tap][oc])
        for (int l = t; l < ICC * 9 * OC1; l += 256)
            ((float*)sw)[l] = g_w1r[ic0 * 9 * OC1 + l];
        // x chunk: ICC ch x 6 rows (y0-1 .. y0+4) x 128 cols, skewed store
        for (int l = t; l < ICC * 6 * 128; l += 256) {
            int col = l & 127;
            int row = (l >> 7) % 6;
            int ch  = l / (6 * 128);
            int gy  = y0 - 1 + row;
            float v = 0.f;
            if (gy >= 0 && gy < NH)
                v = x[((b * NC + ic0 + ch) * NH + gy) * NW + col];
            sx[ch][row][col + 2 * (col >> 5)] = v;
        }
        __syncthreads();

#pragma unroll
        for (int ic = 0; ic < ICC; ic++) {
#pragma unroll
            for (int dy = 0; dy < 3; dy++) {
                float xv[10];
#pragma unroll
                for (int k = 0; k < 10; k++) {
                    int col = p0 + k - 1;
                    if ((octet == 0 && k == 0) || (octet == 15 && k == 9)) {
                        xv[k] = 0.f;
                    } else {
                        xv[k] = sx[ic][r + dy][col + 2 * (col >> 5)];
                    }
                }
#pragma unroll
                for (int dx = 0; dx < 3; dx++) {
                    float4 w4 = *(const float4*)&sw[ic][dy * 3 + dx][ocg * 4];
#pragma unroll
                    for (int p = 0; p < 8; p++) {
                        float xvv = xv[p + dx];
                        acc[0][p] += w4.x * xvv;
                        acc[1][p] += w4.y * xvv;
                        acc[2][p] += w4.z * xvv;
                        acc[3][p] += w4.w * xvv;
                    }
                }
            }
        }
        __syncthreads();
    }

    // relu + vectorized store: 4 oc x 2 float4
#pragma unroll
    for (int j = 0; j < 4; j++) {
        int oc = ocg * 4 + j;
        float* dst = &g_h[((b * OC1 + oc) * NH + (y0 + r)) * NW + p0];
        float4 v0, v1;
        v0.x = fmaxf(acc[j][0], 0.f); v0.y = fmaxf(acc[j][1], 0.f);
        v0.z = fmaxf(acc[j][2], 0.f); v0.w = fmaxf(acc[j][3], 0.f);
        v1.x = fmaxf(acc[j][4], 0.f); v1.y = fmaxf(acc[j][5], 0.f);
        v1.z = fmaxf(acc[j][6], 0.f); v1.w = fmaxf(acc[j][7], 0.f);
        ((float4*)dst)[0] = v0;
        ((float4*)dst)[1] = v1;
    }
}

// ---------------------------------------------------------------------------
// conv2 + sigmoid: g_h[b,16,H,W] -> g_A[b,H,W]
// Block: (b, 8-row tile). 128 threads: octet(16) x row(8); thread = 8 pixels.
// Tiny workload; direct __ldg (L1-resident: h tile reused by neighbors).
// ---------------------------------------------------------------------------
__global__ __launch_bounds__(128) void conv2_kernel(const float* __restrict__ w2) {
    const int b  = blockIdx.y;
    const int y  = blockIdx.x * 8 + (threadIdx.x >> 4);
    const int p0 = (threadIdx.x & 15) * 8;

    float acc[8];
#pragma unroll
    for (int p = 0; p < 8; p++) acc[p] = 0.f;

    for (int ic = 0; ic < OC1; ic++) {
#pragma unroll
        for (int dy = 0; dy < 3; dy++) {
            int gy = y + dy - 1;
            float xv[10];
            if (gy >= 0 && gy < NH) {
                const float* row = &g_h[((b * OC1 + ic) * NH + gy) * NW];
#pragma unroll
                for (int k = 0; k < 10; k++) {
                    int col = p0 + k - 1;
                    xv[k] = (col >= 0 && col < NW) ? __ldg(row + col) : 0.f;
                }
            } else {
#pragma unroll
                for (int k = 0; k < 10; k++) xv[k] = 0.f;
            }
#pragma unroll
            for (int dx = 0; dx < 3; dx++) {
                float w = __ldg(&w2[ic * 9 + dy * 3 + dx]);
#pragma unroll
                for (int p = 0; p < 8; p++) acc[p] += w * xv[p + dx];
            }
        }
    }

    float* dst = &g_A[(b * NH + y) * NW + p0];
    float4 v0, v1;
    v0.x = 1.f / (1.f + __expf(-acc[0])); v0.y = 1.f / (1.f + __expf(-acc[1]));
    v0.z = 1.f / (1.f + __expf(-acc[2])); v0.w = 1.f / (1.f + __expf(-acc[3]));
    v1.x = 1.f / (1.f + __expf(-acc[4])); v1.y = 1.f / (1.f + __expf(-acc[5]));
    v1.z = 1.f / (1.f + __expf(-acc[6])); v1.w = 1.f / (1.f + __expf(-acc[7]));
    ((float4*)dst)[0] = v0;
    ((float4*)dst)[1] = v1;
}

// ---------------------------------------------------------------------------
// out = x * boxsum3x3(A). Thread handles 4 cols x 1 row x all 64 channels,
// computing the box once and streaming x float4 (pure bandwidth).
// ---------------------------------------------------------------------------
__global__ __launch_bounds__(256) void box_mul_kernel(const float* __restrict__ x,
                                                      float* __restrict__ out) {
    int g  = blockIdx.x * 256 + threadIdx.x;   // 32*128*32 threads
    int xg = g & 31;
    int y  = (g >> 5) & 127;
    int b  = g >> 12;
    int x0 = xg * 4;

    const float* Ab = &g_A[b * NH * NW];
    float box[4] = {0.f, 0.f, 0.f, 0.f};
#pragma unroll
    for (int dy = -1; dy <= 1; dy++) {
        int gy = y + dy;
        if (gy < 0 || gy >= NH) continue;
        const float* row = Ab + gy * NW;
        float a[6];
#pragma unroll
        for (int k = 0; k < 6; k++) {
            int col = x0 - 1 + k;
            a[k] = (col >= 0 && col < NW) ? __ldg(row + col) : 0.f;
        }
#pragma unroll
        for (int j = 0; j < 4; j++) box[j] += a[j] + a[j + 1] + a[j + 2];
    }

    int base = (b * NC * NH + y) * NW + x0;    // channel 0 offset
#pragma unroll 4
    for (int c = 0; c < NC; c++) {
        int off = base + c * (NH * NW);
        float4 xv = *(const float4*)&x[off];
        float4 o;
        o.x = xv.x * box[0];
        o.y = xv.y * box[1];
        o.z = xv.z * box[2];
        o.w = xv.w * box[3];
        *(float4*)&out[off] = o;
    }
}

// ---------------------------------------------------------------------------
extern "C" void kernel_launch(void* const* d_in, const int* in_sizes, int n_in,
                              void* d_out, int out_size) {
    const float* x  = (const float*)d_in[0];
    // d_in[1] = dead "weights" arg, unused by the reference forward
    const float* w1 = (const float*)d_in[2];
    const float* w2 = (const float*)d_in[3];
    float* out = (float*)d_out;

    prep_w1_kernel<<<(OC1 * NC * 9 + 255) / 256, 256>>>(w1);
    conv1_kernel<<<dim3(NH / 4, NB), 256>>>(x);
    conv2_kernel<<<dim3(NH / 8, NB), 128>>>(w2);
    box_mul_kernel<<<(NB * NH * (NW / 4)) / 256, 256>>>(x, out);
}

// round 4
// speedup vs baseline: 1.1347x; 1.1347x over previous
#include <cuda_runtime.h>
#include <cuda_bf16.h>

// Problem constants: x[32,64,128,128] f32; w1[16,64,3,3]; w2[1,16,3,3]; out[32,64,128,128] f32
#define NB   32
#define NC   64
#define NH   128
#define NW   128
#define OC1  16

// Scratch (allocation-free rule: __device__ globals)
__device__ float g_h[NB * OC1 * NH * NW];    // conv1+relu output, 33.5 MB
__device__ float g_A[NB * NH * NW];          // sigmoid attention map, 2 MB
__device__ float g_w1r[NC * 9 * OC1];        // w1 transposed to [ic][tap][oc]

// ---- packed f32x2 helpers (sm_100+) ---------------------------------------
__device__ __forceinline__ unsigned long long pk2(float lo, float hi) {
    unsigned long long r;
    asm("mov.b64 %0, {%1, %2};" : "=l"(r) : "f"(lo), "f"(hi));
    return r;
}
__device__ __forceinline__ void upk2(float& lo, float& hi, unsigned long long v) {
    asm("mov.b64 {%0, %1}, %2;" : "=f"(lo), "=f"(hi) : "l"(v));
}
__device__ __forceinline__ void fma2(unsigned long long& d,
                                     unsigned long long a,
                                     unsigned long long b) {
    asm("fma.rn.f32x2 %0, %1, %2, %0;" : "+l"(d) : "l"(a), "l"(b));
}

// ---------------------------------------------------------------------------
// Prep: w1 [oc][ic][ky][kx] -> g_w1r [ic][tap][oc]  (oc contiguous)
// ---------------------------------------------------------------------------
__global__ void prep_w1_kernel(const float* __restrict__ w1) {
    int i = blockIdx.x * 256 + threadIdx.x;
    if (i < OC1 * NC * 9) {
        int t  = i % 9;
        int ic = (i / 9) % NC;
        int oc = i / (9 * NC);
        g_w1r[(ic * 9 + t) * OC1 + oc] = w1[i];
    }
}

// ---------------------------------------------------------------------------
// conv1 + relu: x[b,64,H,W] -> g_h[b,16,H,W], packed FFMA2 inner loop.
// Block: (b, 4-row tile). 256 threads: octet(16) x ocg(4) x row(4).
// Thread computes 4 out-channels (as 2 f32x2 pairs) x 8 consecutive pixels.
// ---------------------------------------------------------------------------
#define ICC   8      // input-channel chunk
#define RPAD  134    // 128 + skew headroom

__global__ __launch_bounds__(256) void conv1_kernel(const float* __restrict__ x) {
    __shared__ float sx[ICC][6][RPAD];     // 25.7 KB
    __shared__ float sw[ICC][9][OC1];      //  4.5 KB

    const int b     = blockIdx.y;
    const int y0    = blockIdx.x * 4;
    const int t     = threadIdx.x;
    const int octet = t & 15;
    const int ocg   = (t >> 4) & 3;
    const int r     = t >> 6;
    const int p0    = octet * 8;

    // acc2[j][p]: lo half = oc ocg*4+2j, hi half = oc ocg*4+2j+1, pixel p
    unsigned long long acc2[2][8];
#pragma unroll
    for (int j = 0; j < 2; j++)
#pragma unroll
        for (int p = 0; p < 8; p++) acc2[j][p] = 0ULL;

    for (int ic0 = 0; ic0 < NC; ic0 += ICC) {
        // weights chunk (layout already [ic][tap][oc])
        for (int l = t; l < ICC * 9 * OC1; l += 256)
            ((float*)sw)[l] = g_w1r[ic0 * 9 * OC1 + l];
        // x chunk: ICC ch x 6 rows (y0-1 .. y0+4) x 128 cols, skewed store
        for (int l = t; l < ICC * 6 * 128; l += 256) {
            int col = l & 127;
            int row = (l >> 7) % 6;
            int ch  = l / (6 * 128);
            int gy  = y0 - 1 + row;
            float v = 0.f;
            if (gy >= 0 && gy < NH)
                v = x[((b * NC + ic0 + ch) * NH + gy) * NW + col];
            sx[ch][row][col + 2 * (col >> 5)] = v;
        }
        __syncthreads();

#pragma unroll
        for (int ic = 0; ic < ICC; ic++) {
#pragma unroll
            for (int dy = 0; dy < 3; dy++) {
                float xv[10];
#pragma unroll
                for (int k = 0; k < 10; k++) {
                    int col = p0 + k - 1;
                    if ((octet == 0 && k == 0) || (octet == 15 && k == 9)) {
                        xv[k] = 0.f;
                    } else {
                        xv[k] = sx[ic][r + dy][col + 2 * (col >> 5)];
                    }
                }
                // broadcast-pack each x value once (ALU pipe, reused 3 dx x 2 pairs)
                unsigned long long xp[10];
#pragma unroll
                for (int k = 0; k < 10; k++) xp[k] = pk2(xv[k], xv[k]);
#pragma unroll
                for (int dx = 0; dx < 3; dx++) {
                    float4 w4 = *(const float4*)&sw[ic][dy * 3 + dx][ocg * 4];
                    unsigned long long wp0 = pk2(w4.x, w4.y);
                    unsigned long long wp1 = pk2(w4.z, w4.w);
#pragma unroll
                    for (int p = 0; p < 8; p++) {
                        fma2(acc2[0][p], wp0, xp[p + dx]);
                        fma2(acc2[1][p], wp1, xp[p + dx]);
                    }
                }
            }
        }
        __syncthreads();
    }

    // unpack + relu + vectorized store: 4 oc x 2 float4
    float accf[4][8];
#pragma unroll
    for (int j = 0; j < 2; j++)
#pragma unroll
        for (int p = 0; p < 8; p++)
            upk2(accf[2 * j][p], accf[2 * j + 1][p], acc2[j][p]);

#pragma unroll
    for (int j = 0; j < 4; j++) {
        int oc = ocg * 4 + j;
        float* dst = &g_h[((b * OC1 + oc) * NH + (y0 + r)) * NW + p0];
        float4 v0, v1;
        v0.x = fmaxf(accf[j][0], 0.f); v0.y = fmaxf(accf[j][1], 0.f);
        v0.z = fmaxf(accf[j][2], 0.f); v0.w = fmaxf(accf[j][3], 0.f);
        v1.x = fmaxf(accf[j][4], 0.f); v1.y = fmaxf(accf[j][5], 0.f);
        v1.z = fmaxf(accf[j][6], 0.f); v1.w = fmaxf(accf[j][7], 0.f);
        ((float4*)dst)[0] = v0;
        ((float4*)dst)[1] = v1;
    }
}

// ---------------------------------------------------------------------------
// conv2 + sigmoid: g_h[b,16,H,W] -> g_A[b,H,W]
// ---------------------------------------------------------------------------
__global__ __launch_bounds__(128) void conv2_kernel(const float* __restrict__ w2) {
    const int b  = blockIdx.y;
    const int y  = blockIdx.x * 8 + (threadIdx.x >> 4);
    const int p0 = (threadIdx.x & 15) * 8;

    float acc[8];
#pragma unroll
    for (int p = 0; p < 8; p++) acc[p] = 0.f;

    for (int ic = 0; ic < OC1; ic++) {
#pragma unroll
        for (int dy = 0; dy < 3; dy++) {
            int gy = y + dy - 1;
            float xv[10];
            if (gy >= 0 && gy < NH) {
                const float* row = &g_h[((b * OC1 + ic) * NH + gy) * NW];
#pragma unroll
                for (int k = 0; k < 10; k++) {
                    int col = p0 + k - 1;
                    xv[k] = (col >= 0 && col < NW) ? __ldg(row + col) : 0.f;
                }
            } else {
#pragma unroll
                for (int k = 0; k < 10; k++) xv[k] = 0.f;
            }
#pragma unroll
            for (int dx = 0; dx < 3; dx++) {
                float w = __ldg(&w2[ic * 9 + dy * 3 + dx]);
#pragma unroll
                for (int p = 0; p < 8; p++) acc[p] += w * xv[p + dx];
            }
        }
    }

    float* dst = &g_A[(b * NH + y) * NW + p0];
    float4 v0, v1;
    v0.x = 1.f / (1.f + __expf(-acc[0])); v0.y = 1.f / (1.f + __expf(-acc[1]));
    v0.z = 1.f / (1.f + __expf(-acc[2])); v0.w = 1.f / (1.f + __expf(-acc[3]));
    v1.x = 1.f / (1.f + __expf(-acc[4])); v1.y = 1.f / (1.f + __expf(-acc[5]));
    v1.z = 1.f / (1.f + __expf(-acc[6])); v1.w = 1.f / (1.f + __expf(-acc[7]));
    ((float4*)dst)[0] = v0;
    ((float4*)dst)[1] = v1;
}

// ---------------------------------------------------------------------------
// out = x * boxsum3x3(A). Thread: 4 cols x 1 row x 16 channels (grid.y splits
// the 64 channels 4-ways for occupancy; A re-read is tiny/L2-resident).
// ---------------------------------------------------------------------------
__global__ __launch_bounds__(256) void box_mul_kernel(const float* __restrict__ x,
                                                      float* __restrict__ out) {
    int g  = blockIdx.x * 256 + threadIdx.x;   // 32*128*32 threads
    int xg = g & 31;
    int y  = (g >> 5) & 127;
    int b  = g >> 12;
    int x0 = xg * 4;
    int c0 = blockIdx.y * 16;

    const float* Ab = &g_A[b * NH * NW];
    float box[4] = {0.f, 0.f, 0.f, 0.f};
#pragma unroll
    for (int dy = -1; dy <= 1; dy++) {
        int gy = y + dy;
        if (gy < 0 || gy >= NH) continue;
        const float* row = Ab + gy * NW;
        float a[6];
#pragma unroll
        for (int k = 0; k < 6; k++) {
            int col = x0 - 1 + k;
            a[k] = (col >= 0 && col < NW) ? __ldg(row + col) : 0.f;
        }
#pragma unroll
        for (int j = 0; j < 4; j++) box[j] += a[j] + a[j + 1] + a[j + 2];
    }

    int base = ((b * NC + c0) * NH + y) * NW + x0;
#pragma unroll 4
    for (int c = 0; c < 16; c++) {
        int off = base + c * (NH * NW);
        float4 xv = *(const float4*)&x[off];
        float4 o;
        o.x = xv.x * box[0];
        o.y = xv.y * box[1];
        o.z = xv.z * box[2];
        o.w = xv.w * box[3];
        *(float4*)&out[off] = o;
    }
}

// ---------------------------------------------------------------------------
extern "C" void kernel_launch(void* const* d_in, const int* in_sizes, int n_in,
                              void* d_out, int out_size) {
    const float* x  = (const float*)d_in[0];
    // d_in[1] = dead "weights" arg, unused by the reference forward
    const float* w1 = (const float*)d_in[2];
    const float* w2 = (const float*)d_in[3];
    float* out = (float*)d_out;

    prep_w1_kernel<<<(OC1 * NC * 9 + 255) / 256, 256>>>(w1);
    conv1_kernel<<<dim3(NH / 4, NB), 256>>>(x);
    conv2_kernel<<<dim3(NH / 8, NB), 128>>>(w2);
    box_mul_kernel<<<dim3((NB * NH * (NW / 4)) / 256, 4), 256>>>(x, out);
}